// round 6
// baseline (speedup 1.0000x reference)
#include <cuda_runtime.h>
#include <cuda_bf16.h>
#include <cstdint>

#define NN   4096
#define FIN  256
#define FOUT 256
#define NH   4
#define DD   64
#define ALPHA 0.2f

// ---------------- device scratch (no allocs allowed) ----------------
__device__ float    g_h [NN * FOUT];      // x@W, fp32 exact
__device__ float    g_hr[NN * FOUT];      // tf32-rounded copy (B operand)
__device__ unsigned g_adjbits[NN * (NN / 32)];
__device__ float    g_A[NH * NN];         // exp(si)
__device__ float    g_B[NH * NN];         // exp(alpha*si)
__device__ float2   g_e12[NH * NN];       // {exp(sj), exp(alpha*sj)}
__device__ float    g_atts[2 * NN * FOUT];  // split numerators
__device__ float    g_den[2 * NH * NN];     // split denominators

// ---------------- cp.async helpers ----------------
__device__ __forceinline__ void cp16(uint32_t dst, const void* src) {
    asm volatile("cp.async.cg.shared.global [%0], [%1], 16;\n" :: "r"(dst), "l"(src));
}
__device__ __forceinline__ void cp8(uint32_t dst, const void* src) {
    asm volatile("cp.async.ca.shared.global [%0], [%1], 8;\n" :: "r"(dst), "l"(src));
}
__device__ __forceinline__ void cp_commit() {
    asm volatile("cp.async.commit_group;\n");
}
__device__ __forceinline__ void cp_wait0() {
    asm volatile("cp.async.wait_group 0;\n");
}

// ---------------- kernel 1: pack adj int32 -> bits ----------------
__global__ void pack_adj_kernel(const int* __restrict__ adj) {
    int lane = threadIdx.x & 31;
    size_t gw = (size_t)(blockIdx.x * blockDim.x + threadIdx.x) >> 5;
    const int* base = adj + gw * 1024;
    unsigned myword = 0;
#pragma unroll
    for (int i = 0; i < 32; i++) {
        int v = base[i * 32 + lane];
        unsigned b = __ballot_sync(0xffffffffu, v > 0);
        if (lane == i) myword = b;
    }
    g_adjbits[gw * 32 + lane] = myword;
}

// ---------------- kernel 2: h = x @ W (fp32 SIMT tiled) ----------------
__global__ __launch_bounds__(256) void gemm_h_kernel(const float* __restrict__ x,
                                                     const float* __restrict__ W) {
    __shared__ float xsT[16][68];
    __shared__ float wsm[16][68];
    int t  = threadIdx.x;
    int m0 = blockIdx.x * 64;
    int n0 = blockIdx.y * 64;
    int r0 = (t >> 4) << 2;
    int c0 = (t & 15) << 2;
    float acc[4][4] = {};

    for (int kt = 0; kt < 16; kt++) {
        int k0 = kt * 16;
        {
            int row = t >> 2, c4 = t & 3;
            float4 v = *(const float4*)(x + (size_t)(m0 + row) * FIN + k0 + c4 * 4);
            xsT[c4 * 4 + 0][row] = v.x;
            xsT[c4 * 4 + 1][row] = v.y;
            xsT[c4 * 4 + 2][row] = v.z;
            xsT[c4 * 4 + 3][row] = v.w;
        }
        {
            int r = t >> 4, c4 = t & 15;
            *(float4*)&wsm[r][c4 * 4] =
                *(const float4*)(W + (size_t)(k0 + r) * FOUT + n0 + c4 * 4);
        }
        __syncthreads();
#pragma unroll
        for (int k = 0; k < 16; k++) {
            float4 av = *(float4*)&xsT[k][r0];
            float4 bv = *(float4*)&wsm[k][c0];
            acc[0][0] += av.x * bv.x; acc[0][1] += av.x * bv.y; acc[0][2] += av.x * bv.z; acc[0][3] += av.x * bv.w;
            acc[1][0] += av.y * bv.x; acc[1][1] += av.y * bv.y; acc[1][2] += av.y * bv.z; acc[1][3] += av.y * bv.w;
            acc[2][0] += av.z * bv.x; acc[2][1] += av.z * bv.y; acc[2][2] += av.z * bv.z; acc[2][3] += av.z * bv.w;
            acc[3][0] += av.w * bv.x; acc[3][1] += av.w * bv.y; acc[3][2] += av.w * bv.z; acc[3][3] += av.w * bv.w;
        }
        __syncthreads();
    }
#pragma unroll
    for (int i = 0; i < 4; i++) {
        size_t off = (size_t)(m0 + r0 + i) * FOUT + n0 + c0;
        float4 v = make_float4(acc[i][0], acc[i][1], acc[i][2], acc[i][3]);
        *(float4*)(g_h + off) = v;
        float4 vr;
        unsigned u;
        asm("cvt.rna.tf32.f32 %0, %1;" : "=r"(u) : "f"(v.x)); vr.x = __uint_as_float(u);
        asm("cvt.rna.tf32.f32 %0, %1;" : "=r"(u) : "f"(v.y)); vr.y = __uint_as_float(u);
        asm("cvt.rna.tf32.f32 %0, %1;" : "=r"(u) : "f"(v.z)); vr.z = __uint_as_float(u);
        asm("cvt.rna.tf32.f32 %0, %1;" : "=r"(u) : "f"(v.w)); vr.w = __uint_as_float(u);
        *(float4*)(g_hr + off) = vr;
    }
}

// ---------------- kernel 3: si/sj dots + exp tables ----------------
__global__ void prep_kernel(const float* __restrict__ a) {
    __shared__ float a_s[128];
    int t = threadIdx.x;
    if (t < 128) a_s[t] = a[t];
    __syncthreads();
    int wid  = t >> 5, lane = t & 31;
    int n    = blockIdx.x * 8 + wid;
    int head = lane >> 3;
    int sub  = lane & 7;
    const float4* hrow = (const float4*)(g_h + (size_t)n * FOUT);
    float psi = 0.f, psj = 0.f;
#pragma unroll
    for (int v = 0; v < 2; v++) {
        float4 hv = hrow[lane * 2 + v];
        int db = sub * 8 + v * 4;
        psi += hv.x * a_s[db]      + hv.y * a_s[db + 1]      + hv.z * a_s[db + 2]      + hv.w * a_s[db + 3];
        psj += hv.x * a_s[64 + db] + hv.y * a_s[64 + db + 1] + hv.z * a_s[64 + db + 2] + hv.w * a_s[64 + db + 3];
    }
#pragma unroll
    for (int off = 4; off; off >>= 1) {
        psi += __shfl_down_sync(0xffffffffu, psi, off);
        psj += __shfl_down_sync(0xffffffffu, psj, off);
    }
    if (sub == 0) {
        int idx = head * NN + n;
        g_A[idx]   = expf(psi);
        g_B[idx]   = expf(ALPHA * psi);
        g_e12[idx] = make_float2(expf(psj), expf(ALPHA * psj));
    }
}

// ---------------- kernel 4: fused attention (tf32 mma.sync) ----------------
__device__ __forceinline__ void mma_tf32(float* d, unsigned a0, unsigned a1, unsigned a2,
                                         unsigned a3, unsigned b0, unsigned b1) {
    asm volatile(
        "mma.sync.aligned.m16n8k8.row.col.f32.tf32.tf32.f32 "
        "{%0,%1,%2,%3}, {%4,%5,%6,%7}, {%8,%9}, {%0,%1,%2,%3};\n"
        : "+f"(d[0]), "+f"(d[1]), "+f"(d[2]), "+f"(d[3])
        : "r"(a0), "r"(a1), "r"(a2), "r"(a3), "r"(b0), "r"(b1));
}

__device__ __forceinline__ float cvt_tf32(float x) {
    unsigned u;
    asm("cvt.rna.tf32.f32 %0, %1;" : "=r"(u) : "f"(x));
    return __uint_as_float(u);
}

// smem float offsets
#define OFF_HS   0        // [2][64*72]  = 9216
#define OFF_WT   9216     // [64][68] transposed W (n-major) = 4352
#define OFF_E12  13568    // float2[2][64] = 256 floats
#define OFF_ADJ  13824    // unsigned[2][128] = 256
#define OFF_SP   14080    // 256
#define SMEM_FLOATS 14336 // 57344 bytes

// grid (64, 4, 2): 64-row n-tile, head, m-half.  256 thr, 3 CTA/SM.
__global__ __launch_bounds__(256, 3) void attn_kernel() {
    extern __shared__ float sm[];
    float*    Wt   = sm + OFF_WT;
    float2*   e12b = (float2*)(sm + OFF_E12);    // [2][64]
    unsigned* adjb = (unsigned*)(sm + OFF_ADJ);  // [2][128]
    float*    Sp   = sm + OFF_SP;

    int t  = threadIdx.x;
    int hd = blockIdx.y;
    int n0 = blockIdx.x * 64;
    int z  = blockIdx.z;
    int mz0 = z * (NN / 2);

    uint32_t smem_b = (uint32_t)__cvta_generic_to_shared(sm);
    uint32_t hs_b   = smem_b;
    uint32_t e12_b  = smem_b + OFF_E12 * 4;
    uint32_t adj_b  = smem_b + OFF_ADJ * 4;

    int nl = t & 63, mc = t >> 6;      // w-gen role: n=nl, m strip mc*16..+15
    int lane = t & 31, wid = t >> 5;
    int g   = lane >> 2;
    int tig = lane & 3;
    int wn0 = (wid & 3) * 16;          // warp n offset
    int wd0 = (wid >> 2) * 32;         // warp d offset
    float acc[4][4] = {};
    float sacc = 0.f;

    float An = g_A[hd * NN + n0 + nl];
    float Bn = g_B[hd * NN + n0 + nl];

    // stage tile mt (0..31) into buffer b
    auto stage = [&](int mt, int b) {
        int m0 = mz0 + mt * 64;
        uint32_t hb = hs_b + (uint32_t)b * 4608u * 4u;
#pragma unroll
        for (int r = 0; r < 4; r++) {
            int li = t + r * 256;
            int mi = li >> 4, d4 = li & 15;
            cp16(hb + (uint32_t)(mi * 72 + d4 * 4) * 4u,
                 g_hr + (size_t)(m0 + mi) * FOUT + hd * DD + d4 * 4);
        }
        if (t < 32)
            cp16(e12_b + (uint32_t)b * 512u + (uint32_t)t * 16u,
                 (const char*)(g_e12 + hd * NN + m0) + t * 16);
        if (t >= 64 && t < 128) {
            int rr = t - 64;
            cp8(adj_b + (uint32_t)b * 512u + (uint32_t)rr * 8u,
                g_adjbits + (size_t)(n0 + rr) * (NN / 32) + (m0 >> 5));
        }
    };

    stage(0, 0);
    cp_commit();

    for (int mt = 0; mt < 32; mt++) {
        int p = mt & 1;
        cp_wait0();        // tile mt fully landed (its group committed last)
        __syncthreads();   // ALL warps done reading buffer p^1 (tile mt-1) AND see tile mt
        if (mt < 31) {     // safe now: nobody reads buffer p^1 anymore
            stage(mt + 1, p ^ 1);
            cp_commit();
        }

        // ---- w-gen: 16 elems/thread; wv = max(An*ex, Bn*ey), tf32-rounded ----
        unsigned word = adjb[p * 128 + nl * 2 + (mc >> 1)] >> ((mc & 1) * 16);
        const float4* e4 = (const float4*)(e12b + p * 64 + mc * 16);
        float* wrow = Wt + nl * 68 + mc * 16;
#pragma unroll
        for (int i = 0; i < 16; i += 4) {
            float4 ea = e4[(i >> 1)];
            float4 eb = e4[(i >> 1) + 1];
            float w0 = fmaxf(An * ea.x, Bn * ea.y);
            float w1 = fmaxf(An * ea.z, Bn * ea.w);
            float w2 = fmaxf(An * eb.x, Bn * eb.y);
            float w3 = fmaxf(An * eb.z, Bn * eb.w);
            w0 = ((word >> (i + 0)) & 1u) ? w0 : 0.f;
            w1 = ((word >> (i + 1)) & 1u) ? w1 : 0.f;
            w2 = ((word >> (i + 2)) & 1u) ? w2 : 0.f;
            w3 = ((word >> (i + 3)) & 1u) ? w3 : 0.f;
            w0 = cvt_tf32(w0); w1 = cvt_tf32(w1);
            w2 = cvt_tf32(w2); w3 = cvt_tf32(w3);
            sacc += (w0 + w1) + (w2 + w3);
            *(float4*)(wrow + i) = make_float4(w0, w1, w2, w3);
        }
        __syncthreads();

        // ---- mma: C(64x64) += W(64n x 64m) * H(64m x 64d), 8 k-steps ----
        const float* H = sm + p * 4608;
#pragma unroll
        for (int ks = 0; ks < 8; ks++) {
            int k0 = ks * 8;
            unsigned a0 = __float_as_uint(Wt[(wn0 + g) * 68 + k0 + tig]);
            unsigned a1 = __float_as_uint(Wt[(wn0 + g + 8) * 68 + k0 + tig]);
            unsigned a2 = __float_as_uint(Wt[(wn0 + g) * 68 + k0 + tig + 4]);
            unsigned a3 = __float_as_uint(Wt[(wn0 + g + 8) * 68 + k0 + tig + 4]);
#pragma unroll
            for (int j = 0; j < 4; j++) {
                unsigned b0 = __float_as_uint(H[(k0 + tig) * 72 + wd0 + 8 * j + g]);
                unsigned b1 = __float_as_uint(H[(k0 + tig + 4) * 72 + wd0 + 8 * j + g]);
                mma_tf32(acc[j], a0, a1, a2, a3, b0, b1);
            }
        }
    }

    // partial denominator reduction -> global
    Sp[t] = sacc;
    __syncthreads();
    if (t < 64) {
        float s = Sp[t] + Sp[64 + t] + Sp[128 + t] + Sp[192 + t];
        g_den[(z * NH + hd) * NN + n0 + t] = s;
    }

    // raw numerator store
    float* dst = g_atts + (size_t)z * NN * FOUT;
    int na = n0 + wn0 + g, nb = na + 8;
    int colbase = hd * DD + wd0 + 2 * tig;
#pragma unroll
    for (int j = 0; j < 4; j++) {
        int col = colbase + 8 * j;
        dst[(size_t)na * FOUT + col]     = acc[j][0];
        dst[(size_t)na * FOUT + col + 1] = acc[j][1];
        dst[(size_t)nb * FOUT + col]     = acc[j][2];
        dst[(size_t)nb * FOUT + col + 1] = acc[j][3];
    }
}

// ---------------- kernel 5: combine + LayerNorm ----------------
__global__ void ln_kernel(const float* __restrict__ gamma,
                          const float* __restrict__ beta,
                          float* __restrict__ out) {
    int wid = threadIdx.x >> 5, lane = threadIdx.x & 31;
    int n = blockIdx.x * 8 + wid;
    int hd = lane >> 3;   // head for cols lane*8 .. lane*8+7
    float den = g_den[hd * NN + n] + g_den[(NH + hd) * NN + n];
    float inv = 1.0f / den;
    const float4* r0 = (const float4*)(g_atts + (size_t)n * FOUT);
    const float4* r1 = (const float4*)(g_atts + (size_t)NN * FOUT + (size_t)n * FOUT);
    float4 x0 = r0[lane * 2],     y0 = r1[lane * 2];
    float4 x1 = r0[lane * 2 + 1], y1 = r1[lane * 2 + 1];
    float4 v0 = make_float4((x0.x + y0.x) * inv, (x0.y + y0.y) * inv,
                            (x0.z + y0.z) * inv, (x0.w + y0.w) * inv);
    float4 v1 = make_float4((x1.x + y1.x) * inv, (x1.y + y1.y) * inv,
                            (x1.z + y1.z) * inv, (x1.w + y1.w) * inv);
    float s = v0.x + v0.y + v0.z + v0.w + v1.x + v1.y + v1.z + v1.w;
#pragma unroll
    for (int o = 16; o; o >>= 1) s += __shfl_xor_sync(0xffffffffu, s, o);
    float mu = s * (1.0f / 256.0f);
    float d0x = v0.x - mu, d0y = v0.y - mu, d0z = v0.z - mu, d0w = v0.w - mu;
    float d1x = v1.x - mu, d1y = v1.y - mu, d1z = v1.z - mu, d1w = v1.w - mu;
    float vs = d0x * d0x + d0y * d0y + d0z * d0z + d0w * d0w +
               d1x * d1x + d1y * d1y + d1z * d1z + d1w * d1w;
#pragma unroll
    for (int o = 16; o; o >>= 1) vs += __shfl_xor_sync(0xffffffffu, vs, o);
    float rs = rsqrtf(vs * (1.0f / 256.0f) + 1e-5f);
    const float4* gp = (const float4*)gamma;
    const float4* bp = (const float4*)beta;
    float4 gm0 = gp[lane * 2], gm1 = gp[lane * 2 + 1];
    float4 bt0 = bp[lane * 2], bt1 = bp[lane * 2 + 1];
    float4 o0 = make_float4(gm0.x * d0x * rs + bt0.x, gm0.y * d0y * rs + bt0.y,
                            gm0.z * d0z * rs + bt0.z, gm0.w * d0w * rs + bt0.w);
    float4 o1 = make_float4(gm1.x * d1x * rs + bt1.x, gm1.y * d1y * rs + bt1.y,
                            gm1.z * d1z * rs + bt1.z, gm1.w * d1w * rs + bt1.w);
    float4* orow = (float4*)(out + (size_t)n * FOUT);
    orow[lane * 2]     = o0;
    orow[lane * 2 + 1] = o1;
}

// ---------------- launch ----------------
extern "C" void kernel_launch(void* const* d_in, const int* in_sizes, int n_in,
                              void* d_out, int out_size) {
    const float* x     = (const float*)d_in[0];
    const int*   adj   = (const int*)d_in[1];
    const float* W     = (const float*)d_in[2];
    const float* a     = (const float*)d_in[3];
    const float* gamma = (const float*)d_in[4];
    const float* beta  = (const float*)d_in[5];
    float* out = (float*)d_out;

    pack_adj_kernel<<<2048, 256>>>(adj);
    gemm_h_kernel<<<dim3(64, 4), 256>>>(x, W);
    prep_kernel<<<512, 256>>>(a);

    size_t shmem = SMEM_FLOATS * sizeof(float);   // 57344 B
    cudaFuncSetAttribute(attn_kernel, cudaFuncAttributeMaxDynamicSharedMemorySize,
                         (int)shmem);
    attn_kernel<<<dim3(64, 4, 2), 256, shmem>>>();

    ln_kernel<<<512, 256>>>(gamma, beta, out);
}

// round 7
// speedup vs baseline: 1.0260x; 1.0260x over previous
#include <cuda_runtime.h>
#include <cuda_bf16.h>
#include <cstdint>

#define NN   4096
#define FIN  256
#define FOUT 256
#define NH   4
#define DD   64
#define ALPHA 0.2f

// ---------------- device scratch (no allocs allowed) ----------------
__device__ float    g_h [NN * FOUT];      // x@W, fp32 (tf32x3 accurate)
__device__ float    g_hr[NN * FOUT];      // tf32-rounded copy (B operand)
__device__ unsigned g_adjbits[NN * (NN / 32)];
__device__ float    g_A[NH * NN];         // exp(si)
__device__ float    g_B[NH * NN];         // exp(alpha*si)
__device__ float2   g_e12[NH * NN];       // {exp(sj), exp(alpha*sj)}
__device__ float    g_atts[2 * NN * FOUT];  // split numerators
__device__ float    g_den[2 * NH * NN];     // split denominators

// ---------------- helpers ----------------
__device__ __forceinline__ void cp16(uint32_t dst, const void* src) {
    asm volatile("cp.async.cg.shared.global [%0], [%1], 16;\n" :: "r"(dst), "l"(src));
}
__device__ __forceinline__ void cp8(uint32_t dst, const void* src) {
    asm volatile("cp.async.ca.shared.global [%0], [%1], 8;\n" :: "r"(dst), "l"(src));
}
__device__ __forceinline__ void cp_commit() {
    asm volatile("cp.async.commit_group;\n");
}
__device__ __forceinline__ void cp_wait0() {
    asm volatile("cp.async.wait_group 0;\n");
}
__device__ __forceinline__ void mma_tf32(float* d, unsigned a0, unsigned a1, unsigned a2,
                                         unsigned a3, unsigned b0, unsigned b1) {
    asm volatile(
        "mma.sync.aligned.m16n8k8.row.col.f32.tf32.tf32.f32 "
        "{%0,%1,%2,%3}, {%4,%5,%6,%7}, {%8,%9}, {%0,%1,%2,%3};\n"
        : "+f"(d[0]), "+f"(d[1]), "+f"(d[2]), "+f"(d[3])
        : "r"(a0), "r"(a1), "r"(a2), "r"(a3), "r"(b0), "r"(b1));
}
__device__ __forceinline__ float cvt_tf32(float x) {
    unsigned u;
    asm("cvt.rna.tf32.f32 %0, %1;" : "=r"(u) : "f"(x));
    return __uint_as_float(u);
}

// ---------------- kernel 1: pack adj int32 -> bits ----------------
__global__ void pack_adj_kernel(const int* __restrict__ adj) {
    int lane = threadIdx.x & 31;
    size_t gw = (size_t)(blockIdx.x * blockDim.x + threadIdx.x) >> 5;
    const int* base = adj + gw * 1024;
    unsigned myword = 0;
#pragma unroll
    for (int i = 0; i < 32; i++) {
        int v = base[i * 32 + lane];
        unsigned b = __ballot_sync(0xffffffffu, v > 0);
        if (lane == i) myword = b;
    }
    g_adjbits[gw * 32 + lane] = myword;
}

// ---------------- kernel 2: h = x @ W via tf32x3 mma (fp32-accurate) ----------------
// grid (64, 2): 64-row m-tile, 128-col n-half. 256 thr, 8 warps (4 m-groups x 2 n-groups).
// smem float offsets (single buffer):
#define GXH 0        // x_hi [64][36] = 2304
#define GXL 2304     // x_lo [64][36]
#define GWH 4608     // W_hi [32][140] = 4480
#define GWL 9088     // W_lo [32][140]
#define GSM 13568    // 54272 bytes

__global__ __launch_bounds__(256) void gemm_h_mma(const float* __restrict__ x,
                                                  const float* __restrict__ W) {
    extern __shared__ float gs[];
    int t = threadIdx.x;
    int m0 = blockIdx.x * 64;
    int byn0 = blockIdx.y * 128;

    int lane = t & 31, wid = t >> 5;
    int g = lane >> 2, tig = lane & 3;
    int wm0 = (wid & 3) * 16;
    int wn0l = (wid >> 2) * 64;

    // staging indices
    int xr = t >> 2, xkc = (t & 3) * 8;      // x: row, k-offset (8 wide)
    int wkr = t >> 3, wnb = (t & 7) * 4;     // W: k-row, col base (4 x strided 32)

    float4 xa, xb, wreg[4];
    auto ldg_tile = [&](int kt) {
        int k0 = kt * 32;
        const float4* xp = (const float4*)(x + (size_t)(m0 + xr) * FIN + k0 + xkc);
        xa = xp[0];
        xb = xp[1];
#pragma unroll
        for (int c = 0; c < 4; c++)
            wreg[c] = *(const float4*)(W + (size_t)(k0 + wkr) * FOUT + byn0 + wnb + 32 * c);
    };
    auto sts_tile = [&]() {
        float4 h, l;
        h = make_float4(cvt_tf32(xa.x), cvt_tf32(xa.y), cvt_tf32(xa.z), cvt_tf32(xa.w));
        l = make_float4(xa.x - h.x, xa.y - h.y, xa.z - h.z, xa.w - h.w);
        *(float4*)&gs[GXH + xr * 36 + xkc] = h;
        *(float4*)&gs[GXL + xr * 36 + xkc] = l;
        h = make_float4(cvt_tf32(xb.x), cvt_tf32(xb.y), cvt_tf32(xb.z), cvt_tf32(xb.w));
        l = make_float4(xb.x - h.x, xb.y - h.y, xb.z - h.z, xb.w - h.w);
        *(float4*)&gs[GXH + xr * 36 + xkc + 4] = h;
        *(float4*)&gs[GXL + xr * 36 + xkc + 4] = l;
#pragma unroll
        for (int c = 0; c < 4; c++) {
            float4 v = wreg[c];
            h = make_float4(cvt_tf32(v.x), cvt_tf32(v.y), cvt_tf32(v.z), cvt_tf32(v.w));
            l = make_float4(v.x - h.x, v.y - h.y, v.z - h.z, v.w - h.w);
            *(float4*)&gs[GWH + wkr * 140 + wnb + 32 * c] = h;
            *(float4*)&gs[GWL + wkr * 140 + wnb + 32 * c] = l;
        }
    };

    float acc[8][4] = {};
    ldg_tile(0);
    for (int kt = 0; kt < 8; kt++) {
        if (kt) __syncthreads();       // previous compute done before overwrite
        sts_tile();
        __syncthreads();
        if (kt < 7) ldg_tile(kt + 1);  // prefetch next while computing
#pragma unroll
        for (int ks = 0; ks < 4; ks++) {
            int k0s = ks * 8;
            unsigned ah0 = __float_as_uint(gs[GXH + (wm0 + g) * 36 + k0s + tig]);
            unsigned ah1 = __float_as_uint(gs[GXH + (wm0 + g + 8) * 36 + k0s + tig]);
            unsigned ah2 = __float_as_uint(gs[GXH + (wm0 + g) * 36 + k0s + tig + 4]);
            unsigned ah3 = __float_as_uint(gs[GXH + (wm0 + g + 8) * 36 + k0s + tig + 4]);
            unsigned al0 = __float_as_uint(gs[GXL + (wm0 + g) * 36 + k0s + tig]);
            unsigned al1 = __float_as_uint(gs[GXL + (wm0 + g + 8) * 36 + k0s + tig]);
            unsigned al2 = __float_as_uint(gs[GXL + (wm0 + g) * 36 + k0s + tig + 4]);
            unsigned al3 = __float_as_uint(gs[GXL + (wm0 + g + 8) * 36 + k0s + tig + 4]);
#pragma unroll
            for (int j = 0; j < 8; j++) {
                int bo = (k0s + tig) * 140 + wn0l + 8 * j + g;
                int bo4 = (k0s + tig + 4) * 140 + wn0l + 8 * j + g;
                unsigned bh0 = __float_as_uint(gs[GWH + bo]);
                unsigned bh1 = __float_as_uint(gs[GWH + bo4]);
                unsigned bl0 = __float_as_uint(gs[GWL + bo]);
                unsigned bl1 = __float_as_uint(gs[GWL + bo4]);
                mma_tf32(acc[j], ah0, ah1, ah2, ah3, bh0, bh1);
                mma_tf32(acc[j], ah0, ah1, ah2, ah3, bl0, bl1);
                mma_tf32(acc[j], al0, al1, al2, al3, bh0, bh1);
            }
        }
    }

    int r0 = m0 + wm0 + g, r1 = r0 + 8;
#pragma unroll
    for (int j = 0; j < 8; j++) {
        int cg = byn0 + wn0l + 8 * j + 2 * tig;
        *(float2*)(g_h + (size_t)r0 * FOUT + cg) = make_float2(acc[j][0], acc[j][1]);
        *(float2*)(g_h + (size_t)r1 * FOUT + cg) = make_float2(acc[j][2], acc[j][3]);
        *(float2*)(g_hr + (size_t)r0 * FOUT + cg) =
            make_float2(cvt_tf32(acc[j][0]), cvt_tf32(acc[j][1]));
        *(float2*)(g_hr + (size_t)r1 * FOUT + cg) =
            make_float2(cvt_tf32(acc[j][2]), cvt_tf32(acc[j][3]));
    }
}

// ---------------- kernel 3: si/sj dots + exp tables ----------------
__global__ void prep_kernel(const float* __restrict__ a) {
    __shared__ float a_s[128];
    int t = threadIdx.x;
    if (t < 128) a_s[t] = a[t];
    __syncthreads();
    int wid  = t >> 5, lane = t & 31;
    int n    = blockIdx.x * 8 + wid;
    int head = lane >> 3;
    int sub  = lane & 7;
    const float4* hrow = (const float4*)(g_h + (size_t)n * FOUT);
    float psi = 0.f, psj = 0.f;
#pragma unroll
    for (int v = 0; v < 2; v++) {
        float4 hv = hrow[lane * 2 + v];
        int db = sub * 8 + v * 4;
        psi += hv.x * a_s[db]      + hv.y * a_s[db + 1]      + hv.z * a_s[db + 2]      + hv.w * a_s[db + 3];
        psj += hv.x * a_s[64 + db] + hv.y * a_s[64 + db + 1] + hv.z * a_s[64 + db + 2] + hv.w * a_s[64 + db + 3];
    }
#pragma unroll
    for (int off = 4; off; off >>= 1) {
        psi += __shfl_down_sync(0xffffffffu, psi, off);
        psj += __shfl_down_sync(0xffffffffu, psj, off);
    }
    if (sub == 0) {
        int idx = head * NN + n;
        g_A[idx]   = expf(psi);
        g_B[idx]   = expf(ALPHA * psi);
        g_e12[idx] = make_float2(expf(psj), expf(ALPHA * psj));
    }
}

// ---------------- kernel 4: fused attention (tf32 mma.sync) — unchanged from R6 ----------------
#define OFF_HS   0        // [2][64*72]  = 9216
#define OFF_WT   9216     // [64][68] transposed W (n-major) = 4352
#define OFF_E12  13568    // float2[2][64] = 256 floats
#define OFF_ADJ  13824    // unsigned[2][128] = 256
#define OFF_SP   14080    // 256
#define SMEM_FLOATS 14336 // 57344 bytes

__global__ __launch_bounds__(256, 3) void attn_kernel() {
    extern __shared__ float sm[];
    float*    Wt   = sm + OFF_WT;
    float2*   e12b = (float2*)(sm + OFF_E12);    // [2][64]
    unsigned* adjb = (unsigned*)(sm + OFF_ADJ);  // [2][128]
    float*    Sp   = sm + OFF_SP;

    int t  = threadIdx.x;
    int hd = blockIdx.y;
    int n0 = blockIdx.x * 64;
    int z  = blockIdx.z;
    int mz0 = z * (NN / 2);

    uint32_t smem_b = (uint32_t)__cvta_generic_to_shared(sm);
    uint32_t hs_b   = smem_b;
    uint32_t e12_b  = smem_b + OFF_E12 * 4;
    uint32_t adj_b  = smem_b + OFF_ADJ * 4;

    int nl = t & 63, mc = t >> 6;
    int lane = t & 31, wid = t >> 5;
    int g   = lane >> 2;
    int tig = lane & 3;
    int wn0 = (wid & 3) * 16;
    int wd0 = (wid >> 2) * 32;
    float acc[4][4] = {};
    float sacc = 0.f;

    float An = g_A[hd * NN + n0 + nl];
    float Bn = g_B[hd * NN + n0 + nl];

    auto stage = [&](int mt, int b) {
        int m0 = mz0 + mt * 64;
        uint32_t hb = hs_b + (uint32_t)b * 4608u * 4u;
#pragma unroll
        for (int r = 0; r < 4; r++) {
            int li = t + r * 256;
            int mi = li >> 4, d4 = li & 15;
            cp16(hb + (uint32_t)(mi * 72 + d4 * 4) * 4u,
                 g_hr + (size_t)(m0 + mi) * FOUT + hd * DD + d4 * 4);
        }
        if (t < 32)
            cp16(e12_b + (uint32_t)b * 512u + (uint32_t)t * 16u,
                 (const char*)(g_e12 + hd * NN + m0) + t * 16);
        if (t >= 64 && t < 128) {
            int rr = t - 64;
            cp8(adj_b + (uint32_t)b * 512u + (uint32_t)rr * 8u,
                g_adjbits + (size_t)(n0 + rr) * (NN / 32) + (m0 >> 5));
        }
    };

    stage(0, 0);
    cp_commit();

    for (int mt = 0; mt < 32; mt++) {
        int p = mt & 1;
        cp_wait0();
        __syncthreads();
        if (mt < 31) {
            stage(mt + 1, p ^ 1);
            cp_commit();
        }

        unsigned word = adjb[p * 128 + nl * 2 + (mc >> 1)] >> ((mc & 1) * 16);
        const float4* e4 = (const float4*)(e12b + p * 64 + mc * 16);
        float* wrow = Wt + nl * 68 + mc * 16;
#pragma unroll
        for (int i = 0; i < 16; i += 4) {
            float4 ea = e4[(i >> 1)];
            float4 eb = e4[(i >> 1) + 1];
            float w0 = fmaxf(An * ea.x, Bn * ea.y);
            float w1 = fmaxf(An * ea.z, Bn * ea.w);
            float w2 = fmaxf(An * eb.x, Bn * eb.y);
            float w3 = fmaxf(An * eb.z, Bn * eb.w);
            w0 = ((word >> (i + 0)) & 1u) ? w0 : 0.f;
            w1 = ((word >> (i + 1)) & 1u) ? w1 : 0.f;
            w2 = ((word >> (i + 2)) & 1u) ? w2 : 0.f;
            w3 = ((word >> (i + 3)) & 1u) ? w3 : 0.f;
            w0 = cvt_tf32(w0); w1 = cvt_tf32(w1);
            w2 = cvt_tf32(w2); w3 = cvt_tf32(w3);
            sacc += (w0 + w1) + (w2 + w3);
            *(float4*)(wrow + i) = make_float4(w0, w1, w2, w3);
        }
        __syncthreads();

        const float* H = sm + p * 4608;
#pragma unroll
        for (int ks = 0; ks < 8; ks++) {
            int k0 = ks * 8;
            unsigned a0 = __float_as_uint(Wt[(wn0 + g) * 68 + k0 + tig]);
            unsigned a1 = __float_as_uint(Wt[(wn0 + g + 8) * 68 + k0 + tig]);
            unsigned a2 = __float_as_uint(Wt[(wn0 + g) * 68 + k0 + tig + 4]);
            unsigned a3 = __float_as_uint(Wt[(wn0 + g + 8) * 68 + k0 + tig + 4]);
#pragma unroll
            for (int j = 0; j < 4; j++) {
                unsigned b0 = __float_as_uint(H[(k0 + tig) * 72 + wd0 + 8 * j + g]);
                unsigned b1 = __float_as_uint(H[(k0 + tig + 4) * 72 + wd0 + 8 * j + g]);
                mma_tf32(acc[j], a0, a1, a2, a3, b0, b1);
            }
        }
    }

    Sp[t] = sacc;
    __syncthreads();
    if (t < 64) {
        float s = Sp[t] + Sp[64 + t] + Sp[128 + t] + Sp[192 + t];
        g_den[(z * NH + hd) * NN + n0 + t] = s;
    }

    float* dst = g_atts + (size_t)z * NN * FOUT;
    int na = n0 + wn0 + g, nb = na + 8;
    int colbase = hd * DD + wd0 + 2 * tig;
#pragma unroll
    for (int j = 0; j < 4; j++) {
        int col = colbase + 8 * j;
        dst[(size_t)na * FOUT + col]     = acc[j][0];
        dst[(size_t)na * FOUT + col + 1] = acc[j][1];
        dst[(size_t)nb * FOUT + col]     = acc[j][2];
        dst[(size_t)nb * FOUT + col + 1] = acc[j][3];
    }
}

// ---------------- kernel 5: combine + LayerNorm ----------------
__global__ void ln_kernel(const float* __restrict__ gamma,
                          const float* __restrict__ beta,
                          float* __restrict__ out) {
    int wid = threadIdx.x >> 5, lane = threadIdx.x & 31;
    int n = blockIdx.x * 8 + wid;
    int hd = lane >> 3;
    float den = g_den[hd * NN + n] + g_den[(NH + hd) * NN + n];
    float inv = 1.0f / den;
    const float4* r0 = (const float4*)(g_atts + (size_t)n * FOUT);
    const float4* r1 = (const float4*)(g_atts + (size_t)NN * FOUT + (size_t)n * FOUT);
    float4 x0 = r0[lane * 2],     y0 = r1[lane * 2];
    float4 x1 = r0[lane * 2 + 1], y1 = r1[lane * 2 + 1];
    float4 v0 = make_float4((x0.x + y0.x) * inv, (x0.y + y0.y) * inv,
                            (x0.z + y0.z) * inv, (x0.w + y0.w) * inv);
    float4 v1 = make_float4((x1.x + y1.x) * inv, (x1.y + y1.y) * inv,
                            (x1.z + y1.z) * inv, (x1.w + y1.w) * inv);
    float s = v0.x + v0.y + v0.z + v0.w + v1.x + v1.y + v1.z + v1.w;
#pragma unroll
    for (int o = 16; o; o >>= 1) s += __shfl_xor_sync(0xffffffffu, s, o);
    float mu = s * (1.0f / 256.0f);
    float d0x = v0.x - mu, d0y = v0.y - mu, d0z = v0.z - mu, d0w = v0.w - mu;
    float d1x = v1.x - mu, d1y = v1.y - mu, d1z = v1.z - mu, d1w = v1.w - mu;
    float vs = d0x * d0x + d0y * d0y + d0z * d0z + d0w * d0w +
               d1x * d1x + d1y * d1y + d1z * d1z + d1w * d1w;
#pragma unroll
    for (int o = 16; o; o >>= 1) vs += __shfl_xor_sync(0xffffffffu, vs, o);
    float rs = rsqrtf(vs * (1.0f / 256.0f) + 1e-5f);
    const float4* gp = (const float4*)gamma;
    const float4* bp = (const float4*)beta;
    float4 gm0 = gp[lane * 2], gm1 = gp[lane * 2 + 1];
    float4 bt0 = bp[lane * 2], bt1 = bp[lane * 2 + 1];
    float4 o0 = make_float4(gm0.x * d0x * rs + bt0.x, gm0.y * d0y * rs + bt0.y,
                            gm0.z * d0z * rs + bt0.z, gm0.w * d0w * rs + bt0.w);
    float4 o1 = make_float4(gm1.x * d1x * rs + bt1.x, gm1.y * d1y * rs + bt1.y,
                            gm1.z * d1z * rs + bt1.z, gm1.w * d1w * rs + bt1.w);
    float4* orow = (float4*)(out + (size_t)n * FOUT);
    orow[lane * 2]     = o0;
    orow[lane * 2 + 1] = o1;
}

// ---------------- launch ----------------
extern "C" void kernel_launch(void* const* d_in, const int* in_sizes, int n_in,
                              void* d_out, int out_size) {
    const float* x     = (const float*)d_in[0];
    const int*   adj   = (const int*)d_in[1];
    const float* W     = (const float*)d_in[2];
    const float* a     = (const float*)d_in[3];
    const float* gamma = (const float*)d_in[4];
    const float* beta  = (const float*)d_in[5];
    float* out = (float*)d_out;

    pack_adj_kernel<<<2048, 256>>>(adj);

    size_t gshmem = GSM * sizeof(float);          // 54272 B
    cudaFuncSetAttribute(gemm_h_mma, cudaFuncAttributeMaxDynamicSharedMemorySize,
                         (int)gshmem);
    gemm_h_mma<<<dim3(64, 2), 256, gshmem>>>(x, W);

    prep_kernel<<<512, 256>>>(a);

    size_t shmem = SMEM_FLOATS * sizeof(float);   // 57344 B
    cudaFuncSetAttribute(attn_kernel, cudaFuncAttributeMaxDynamicSharedMemorySize,
                         (int)shmem);
    attn_kernel<<<dim3(64, 4, 2), 256, shmem>>>();

    ln_kernel<<<512, 256>>>(gamma, beta, out);
}

// round 9
// speedup vs baseline: 1.5490x; 1.5098x over previous
#include <cuda_runtime.h>
#include <cuda_fp16.h>
#include <cstdint>

#define NN   4096
#define FIN  256
#define FOUT 256
#define NH   4
#define DD   64
#define ALPHA 0.2f

// ---------------- device scratch (no allocs allowed) ----------------
__device__ float    g_h [NN * FOUT];        // x@W fp32 (tf32x3 accurate) - for prep
__device__ __half   g_hf[NN * FOUT];        // fp16 copy (B operand source)
__device__ unsigned g_adjbits[NN * (NN / 32)];
__device__ float    g_A[NH * NN];           // exp(si)
__device__ float    g_B[NH * NN];           // exp(alpha*si)
__device__ float2   g_e12[NH * NN];         // {exp(sj), exp(alpha*sj)}
__device__ unsigned g_emaxu[NH];            // max_m exp(sj) per head (bits)
__device__ float    g_atts[2 * NN * FOUT];  // split numerators
__device__ float    g_den[2 * NH * NN];     // split denominators

// ---------------- helpers ----------------
__device__ __forceinline__ void cp16(uint32_t dst, const void* src) {
    asm volatile("cp.async.cg.shared.global [%0], [%1], 16;\n" :: "r"(dst), "l"(src));
}
__device__ __forceinline__ void cp8(uint32_t dst, const void* src) {
    asm volatile("cp.async.ca.shared.global [%0], [%1], 8;\n" :: "r"(dst), "l"(src));
}
__device__ __forceinline__ void cp_commit() {
    asm volatile("cp.async.commit_group;\n");
}
__device__ __forceinline__ void cp_wait0() {
    asm volatile("cp.async.wait_group 0;\n");
}
__device__ __forceinline__ void mma_tf32(float* d, unsigned a0, unsigned a1, unsigned a2,
                                         unsigned a3, unsigned b0, unsigned b1) {
    asm volatile(
        "mma.sync.aligned.m16n8k8.row.col.f32.tf32.tf32.f32 "
        "{%0,%1,%2,%3}, {%4,%5,%6,%7}, {%8,%9}, {%0,%1,%2,%3};\n"
        : "+f"(d[0]), "+f"(d[1]), "+f"(d[2]), "+f"(d[3])
        : "r"(a0), "r"(a1), "r"(a2), "r"(a3), "r"(b0), "r"(b1));
}
__device__ __forceinline__ void mma_f16(float* d, unsigned a0, unsigned a1, unsigned a2,
                                        unsigned a3, unsigned b0, unsigned b1) {
    asm volatile(
        "mma.sync.aligned.m16n8k16.row.col.f32.f16.f16.f32 "
        "{%0,%1,%2,%3}, {%4,%5,%6,%7}, {%8,%9}, {%0,%1,%2,%3};\n"
        : "+f"(d[0]), "+f"(d[1]), "+f"(d[2]), "+f"(d[3])
        : "r"(a0), "r"(a1), "r"(a2), "r"(a3), "r"(b0), "r"(b1));
}
__device__ __forceinline__ void ldsm_x4(unsigned& r0, unsigned& r1, unsigned& r2,
                                        unsigned& r3, uint32_t addr) {
    asm volatile("ldmatrix.sync.aligned.m8n8.x4.shared.b16 {%0,%1,%2,%3}, [%4];"
                 : "=r"(r0), "=r"(r1), "=r"(r2), "=r"(r3) : "r"(addr));
}
__device__ __forceinline__ void ldsm_x4_t(unsigned& r0, unsigned& r1, unsigned& r2,
                                          unsigned& r3, uint32_t addr) {
    asm volatile("ldmatrix.sync.aligned.m8n8.x4.trans.shared.b16 {%0,%1,%2,%3}, [%4];"
                 : "=r"(r0), "=r"(r1), "=r"(r2), "=r"(r3) : "r"(addr));
}
__device__ __forceinline__ float cvt_tf32(float x) {
    unsigned u;
    asm("cvt.rna.tf32.f32 %0, %1;" : "=r"(u) : "f"(x));
    return __uint_as_float(u);
}

// ---------------- kernel 1: pack adj int32 -> bits (+ init emax) ----------------
__global__ void pack_adj_kernel(const int* __restrict__ adj) {
    if (blockIdx.x == 0 && threadIdx.x < NH) g_emaxu[threadIdx.x] = 0u;
    int lane = threadIdx.x & 31;
    size_t gw = (size_t)(blockIdx.x * blockDim.x + threadIdx.x) >> 5;
    const int* base = adj + gw * 1024;
    unsigned myword = 0;
#pragma unroll
    for (int i = 0; i < 32; i++) {
        int v = base[i * 32 + lane];
        unsigned b = __ballot_sync(0xffffffffu, v > 0);
        if (lane == i) myword = b;
    }
    g_adjbits[gw * 32 + lane] = myword;
}

// ---------------- kernel 2: h = x @ W via tf32x3 mma ----------------
#define GXH 0        // x_hi [64][36]
#define GXL 2304
#define GWH 4608     // W_hi [32][140]
#define GWL 9088
#define GSM 13568    // floats

__global__ __launch_bounds__(256) void gemm_h_mma(const float* __restrict__ x,
                                                  const float* __restrict__ W) {
    extern __shared__ float gs[];
    int t = threadIdx.x;
    int m0 = blockIdx.x * 64;
    int byn0 = blockIdx.y * 128;

    int lane = t & 31, wid = t >> 5;
    int g = lane >> 2, tig = lane & 3;
    int wm0 = (wid & 3) * 16;
    int wn0l = (wid >> 2) * 64;

    int xr = t >> 2, xkc = (t & 3) * 8;
    int wkr = t >> 3, wnb = (t & 7) * 4;

    float4 xa, xb, wreg[4];
    auto ldg_tile = [&](int kt) {
        int k0 = kt * 32;
        const float4* xp = (const float4*)(x + (size_t)(m0 + xr) * FIN + k0 + xkc);
        xa = xp[0];
        xb = xp[1];
#pragma unroll
        for (int c = 0; c < 4; c++)
            wreg[c] = *(const float4*)(W + (size_t)(k0 + wkr) * FOUT + byn0 + wnb + 32 * c);
    };
    auto sts_tile = [&]() {
        float4 h, l;
        h = make_float4(cvt_tf32(xa.x), cvt_tf32(xa.y), cvt_tf32(xa.z), cvt_tf32(xa.w));
        l = make_float4(xa.x - h.x, xa.y - h.y, xa.z - h.z, xa.w - h.w);
        *(float4*)&gs[GXH + xr * 36 + xkc] = h;
        *(float4*)&gs[GXL + xr * 36 + xkc] = l;
        h = make_float4(cvt_tf32(xb.x), cvt_tf32(xb.y), cvt_tf32(xb.z), cvt_tf32(xb.w));
        l = make_float4(xb.x - h.x, xb.y - h.y, xb.z - h.z, xb.w - h.w);
        *(float4*)&gs[GXH + xr * 36 + xkc + 4] = h;
        *(float4*)&gs[GXL + xr * 36 + xkc + 4] = l;
#pragma unroll
        for (int c = 0; c < 4; c++) {
            float4 v = wreg[c];
            h = make_float4(cvt_tf32(v.x), cvt_tf32(v.y), cvt_tf32(v.z), cvt_tf32(v.w));
            l = make_float4(v.x - h.x, v.y - h.y, v.z - h.z, v.w - h.w);
            *(float4*)&gs[GWH + wkr * 140 + wnb + 32 * c] = h;
            *(float4*)&gs[GWL + wkr * 140 + wnb + 32 * c] = l;
        }
    };

    float acc[8][4] = {};
    ldg_tile(0);
    for (int kt = 0; kt < 8; kt++) {
        if (kt) __syncthreads();
        sts_tile();
        __syncthreads();
        if (kt < 7) ldg_tile(kt + 1);
#pragma unroll
        for (int ks = 0; ks < 4; ks++) {
            int k0s = ks * 8;
            unsigned ah0 = __float_as_uint(gs[GXH + (wm0 + g) * 36 + k0s + tig]);
            unsigned ah1 = __float_as_uint(gs[GXH + (wm0 + g + 8) * 36 + k0s + tig]);
            unsigned ah2 = __float_as_uint(gs[GXH + (wm0 + g) * 36 + k0s + tig + 4]);
            unsigned ah3 = __float_as_uint(gs[GXH + (wm0 + g + 8) * 36 + k0s + tig + 4]);
            unsigned al0 = __float_as_uint(gs[GXL + (wm0 + g) * 36 + k0s + tig]);
            unsigned al1 = __float_as_uint(gs[GXL + (wm0 + g + 8) * 36 + k0s + tig]);
            unsigned al2 = __float_as_uint(gs[GXL + (wm0 + g) * 36 + k0s + tig + 4]);
            unsigned al3 = __float_as_uint(gs[GXL + (wm0 + g + 8) * 36 + k0s + tig + 4]);
#pragma unroll
            for (int j = 0; j < 8; j++) {
                int bo = (k0s + tig) * 140 + wn0l + 8 * j + g;
                int bo4 = (k0s + tig + 4) * 140 + wn0l + 8 * j + g;
                unsigned bh0 = __float_as_uint(gs[GWH + bo]);
                unsigned bh1 = __float_as_uint(gs[GWH + bo4]);
                unsigned bl0 = __float_as_uint(gs[GWL + bo]);
                unsigned bl1 = __float_as_uint(gs[GWL + bo4]);
                mma_tf32(acc[j], ah0, ah1, ah2, ah3, bh0, bh1);
                mma_tf32(acc[j], ah0, ah1, ah2, ah3, bl0, bl1);
                mma_tf32(acc[j], al0, al1, al2, al3, bh0, bh1);
            }
        }
    }

    int r0 = m0 + wm0 + g, r1 = r0 + 8;
#pragma unroll
    for (int j = 0; j < 8; j++) {
        int cg = byn0 + wn0l + 8 * j + 2 * tig;
        *(float2*)(g_h + (size_t)r0 * FOUT + cg) = make_float2(acc[j][0], acc[j][1]);
        *(float2*)(g_h + (size_t)r1 * FOUT + cg) = make_float2(acc[j][2], acc[j][3]);
        *(__half2*)(g_hf + (size_t)r0 * FOUT + cg) = __floats2half2_rn(acc[j][0], acc[j][1]);
        *(__half2*)(g_hf + (size_t)r1 * FOUT + cg) = __floats2half2_rn(acc[j][2], acc[j][3]);
    }
}

// ---------------- kernel 3: si/sj dots + exp tables + head max ----------------
__global__ void prep_kernel(const float* __restrict__ a) {
    __shared__ float a_s[128];
    int t = threadIdx.x;
    if (t < 128) a_s[t] = a[t];
    __syncthreads();
    int wid  = t >> 5, lane = t & 31;
    int n    = blockIdx.x * 8 + wid;
    int head = lane >> 3;
    int sub  = lane & 7;
    const float4* hrow = (const float4*)(g_h + (size_t)n * FOUT);
    float psi = 0.f, psj = 0.f;
#pragma unroll
    for (int v = 0; v < 2; v++) {
        float4 hv = hrow[lane * 2 + v];
        int db = sub * 8 + v * 4;
        psi += hv.x * a_s[db]      + hv.y * a_s[db + 1]      + hv.z * a_s[db + 2]      + hv.w * a_s[db + 3];
        psj += hv.x * a_s[64 + db] + hv.y * a_s[64 + db + 1] + hv.z * a_s[64 + db + 2] + hv.w * a_s[64 + db + 3];
    }
#pragma unroll
    for (int off = 4; off; off >>= 1) {
        psi += __shfl_down_sync(0xffffffffu, psi, off);
        psj += __shfl_down_sync(0xffffffffu, psj, off);
    }
    if (sub == 0) {
        int idx = head * NN + n;
        float e1 = expf(psj);
        g_A[idx]   = expf(psi);
        g_B[idx]   = expf(ALPHA * psi);
        g_e12[idx] = make_float2(e1, expf(ALPHA * psj));
        atomicMax(&g_emaxu[head], __float_as_uint(e1));   // e1 > 0: bit-compare valid
    }
}

// ---------------- kernel 4: fused attention (fp16 mma + ldmatrix) ----------------
// smem BYTE offsets
#define HSB   0        // Hs halves [2][64][72] : 2 x 9216
#define WTB   18432    // Wt halves [64][72]    : 9216
#define E12B  27648    // float2 [2][64]        : 1024
#define ADJB  28672    // uint [2][128]         : 1024
#define SPB   29696    // float [256]           : 1024
#define SMEMB 30720

// grid (64, 4, 2). 256 thr.
__global__ __launch_bounds__(256, 4) void attn_kernel() {
    extern __shared__ char smc[];
    float2*   e12b = (float2*)(smc + E12B);
    unsigned* adjb = (unsigned*)(smc + ADJB);
    float*    Sp   = (float*)(smc + SPB);

    int t  = threadIdx.x;
    int hd = blockIdx.y;
    int n0 = blockIdx.x * 64;
    int z  = blockIdx.z;
    int mz0 = z * (NN / 2);

    uint32_t base = (uint32_t)__cvta_generic_to_shared(smc);

    int nl = t & 63, mc = t >> 6;
    int lane = t & 31, wid = t >> 5;
    int g   = lane >> 2;
    int tig = lane & 3;
    int wn0 = (wid & 3) * 16;
    int wd0 = (wid >> 2) * 32;
    float acc[4][4] = {};
    float sacc = 0.f;

    // row-scaled coefficients (softmax scale-invariant; fp16 overflow guard)
    float An = g_A[hd * NN + n0 + nl];
    float Bn = g_B[hd * NN + n0 + nl];
    {
        float E1x = __uint_as_float(g_emaxu[hd]);
        float E2x = __powf(E1x, ALPHA);
        float s = 16384.f / fmaxf(An * E1x, Bn * E2x);
        An *= s;
        Bn *= s;
    }

    // ldmatrix lane address bases
    int lrow = (lane & 7) + (lane & 8);            // 0..15
    int lhi8 = (lane >> 4) * 8;                    // +8 halves for matrices 2,3
    uint32_t a_base = base + WTB + (uint32_t)(wn0 + lrow) * 144u + (uint32_t)lhi8 * 2u;
    uint32_t b_rowoff = (uint32_t)lrow * 144u + (uint32_t)(wd0 + lhi8) * 2u;

    auto stage = [&](int mt, int b) {
        int m0 = mz0 + mt * 64;
        uint32_t hb = base + HSB + (uint32_t)b * 9216u;
#pragma unroll
        for (int r = 0; r < 2; r++) {
            int li = t + r * 256;
            int mi = li >> 3, c = li & 7;
            cp16(hb + (uint32_t)(mi * 144 + c * 16),
                 g_hf + (size_t)(m0 + mi) * FOUT + hd * DD + c * 8);
        }
        if (t < 32)
            cp16(base + E12B + (uint32_t)b * 512u + (uint32_t)t * 16u,
                 (const char*)(g_e12 + hd * NN + m0) + t * 16);
        if (t >= 64 && t < 128) {
            int rr = t - 64;
            cp8(base + ADJB + (uint32_t)b * 512u + (uint32_t)rr * 8u,
                g_adjbits + (size_t)(n0 + rr) * (NN / 32) + (m0 >> 5));
        }
    };

    stage(0, 0);
    cp_commit();

    for (int mt = 0; mt < 32; mt++) {
        int p = mt & 1;
        cp_wait0();
        __syncthreads();
        if (mt < 31) {
            stage(mt + 1, p ^ 1);
            cp_commit();
        }

        // ---- w-gen: 16 elems/thread, scaled, packed fp16 ----
        unsigned word = adjb[p * 128 + nl * 2 + (mc >> 1)] >> ((mc & 1) * 16);
        const float4* e4 = (const float4*)(e12b + p * 64 + mc * 16);
        unsigned wp[8];
#pragma unroll
        for (int i = 0; i < 16; i += 4) {
            float4 ea = e4[(i >> 1)];
            float4 eb = e4[(i >> 1) + 1];
            float w0 = fmaxf(An * ea.x, Bn * ea.y);
            float w1 = fmaxf(An * ea.z, Bn * ea.w);
            float w2 = fmaxf(An * eb.x, Bn * eb.y);
            float w3 = fmaxf(An * eb.z, Bn * eb.w);
            w0 = ((word >> (i + 0)) & 1u) ? w0 : 0.f;
            w1 = ((word >> (i + 1)) & 1u) ? w1 : 0.f;
            w2 = ((word >> (i + 2)) & 1u) ? w2 : 0.f;
            w3 = ((word >> (i + 3)) & 1u) ? w3 : 0.f;
            sacc += (w0 + w1) + (w2 + w3);
            __half2 h01 = __floats2half2_rn(w0, w1);
            __half2 h23 = __floats2half2_rn(w2, w3);
            wp[(i >> 1)]     = *(unsigned*)&h01;
            wp[(i >> 1) + 1] = *(unsigned*)&h23;
        }
        {
            uint4* wr = (uint4*)(smc + WTB + nl * 144 + mc * 32);
            wr[0] = make_uint4(wp[0], wp[1], wp[2], wp[3]);
            wr[1] = make_uint4(wp[4], wp[5], wp[6], wp[7]);
        }
        __syncthreads();

        // ---- mma: C(64x64) += W(64n x 64m) * H(64m x 64d), 4 k16-steps ----
        uint32_t hs = base + HSB + (uint32_t)p * 9216u;
#pragma unroll
        for (int ks = 0; ks < 4; ks++) {
            unsigned a0, a1, a2, a3;
            ldsm_x4(a0, a1, a2, a3, a_base + (uint32_t)ks * 32u);
#pragma unroll
            for (int dc = 0; dc < 2; dc++) {
                unsigned r0, r1, r2, r3;
                ldsm_x4_t(r0, r1, r2, r3,
                          hs + b_rowoff + (uint32_t)(ks * 16) * 144u + (uint32_t)dc * 32u);
                mma_f16(acc[2 * dc],     a0, a1, a2, a3, r0, r1);
                mma_f16(acc[2 * dc + 1], a0, a1, a2, a3, r2, r3);
            }
        }
    }

    // partial denominator reduction -> global (scaled domain)
    Sp[t] = sacc;
    __syncthreads();
    if (t < 64) {
        float s = Sp[t] + Sp[64 + t] + Sp[128 + t] + Sp[192 + t];
        g_den[(z * NH + hd) * NN + n0 + t] = s;
    }

    // raw (scaled) numerator store
    float* dst = g_atts + (size_t)z * NN * FOUT;
    int na = n0 + wn0 + g, nb = na + 8;
    int colbase = hd * DD + wd0 + 2 * tig;
#pragma unroll
    for (int j = 0; j < 4; j++) {
        int col = colbase + 8 * j;
        dst[(size_t)na * FOUT + col]     = acc[j][0];
        dst[(size_t)na * FOUT + col + 1] = acc[j][1];
        dst[(size_t)nb * FOUT + col]     = acc[j][2];
        dst[(size_t)nb * FOUT + col + 1] = acc[j][3];
    }
}

// ---------------- kernel 5: combine + LayerNorm ----------------
__global__ void ln_kernel(const float* __restrict__ gamma,
                          const float* __restrict__ beta,
                          float* __restrict__ out) {
    int wid = threadIdx.x >> 5, lane = threadIdx.x & 31;
    int n = blockIdx.x * 8 + wid;
    int hd = lane >> 3;
    float den = g_den[hd * NN + n] + g_den[(NH + hd) * NN + n];
    float inv = 1.0f / den;
    const float4* r0 = (const float4*)(g_atts + (size_t)n * FOUT);
    const float4* r1 = (const float4*)(g_atts + (size_t)NN * FOUT + (size_t)n * FOUT);
    float4 x0 = r0[lane * 2],     y0 = r1[lane * 2];
    float4 x1 = r0[lane * 2 + 1], y1 = r1[lane * 2 + 1];
    float4 v0 = make_float4((x0.x + y0.x) * inv, (x0.y + y0.y) * inv,
                            (x0.z + y0.z) * inv, (x0.w + y0.w) * inv);
    float4 v1 = make_float4((x1.x + y1.x) * inv, (x1.y + y1.y) * inv,
                            (x1.z + y1.z) * inv, (x1.w + y1.w) * inv);
    float s = v0.x + v0.y + v0.z + v0.w + v1.x + v1.y + v1.z + v1.w;
#pragma unroll
    for (int o = 16; o; o >>= 1) s += __shfl_xor_sync(0xffffffffu, s, o);
    float mu = s * (1.0f / 256.0f);
    float d0x = v0.x - mu, d0y = v0.y - mu, d0z = v0.z - mu, d0w = v0.w - mu;
    float d1x = v1.x - mu, d1y = v1.y - mu, d1z = v1.z - mu, d1w = v1.w - mu;
    float vs = d0x * d0x + d0y * d0y + d0z * d0z + d0w * d0w +
               d1x * d1x + d1y * d1y + d1z * d1z + d1w * d1w;
#pragma unroll
    for (int o = 16; o; o >>= 1) vs += __shfl_xor_sync(0xffffffffu, vs, o);
    float rs = rsqrtf(vs * (1.0f / 256.0f) + 1e-5f);
    const float4* gp = (const float4*)gamma;
    const float4* bp = (const float4*)beta;
    float4 gm0 = gp[lane * 2], gm1 = gp[lane * 2 + 1];
    float4 bt0 = bp[lane * 2], bt1 = bp[lane * 2 + 1];
    float4 o0 = make_float4(gm0.x * d0x * rs + bt0.x, gm0.y * d0y * rs + bt0.y,
                            gm0.z * d0z * rs + bt0.z, gm0.w * d0w * rs + bt0.w);
    float4 o1 = make_float4(gm1.x * d1x * rs + bt1.x, gm1.y * d1y * rs + bt1.y,
                            gm1.z * d1z * rs + bt1.z, gm1.w * d1w * rs + bt1.w);
    float4* orow = (float4*)(out + (size_t)n * FOUT);
    orow[lane * 2]     = o0;
    orow[lane * 2 + 1] = o1;
}

// ---------------- launch ----------------
extern "C" void kernel_launch(void* const* d_in, const int* in_sizes, int n_in,
                              void* d_out, int out_size) {
    const float* x     = (const float*)d_in[0];
    const int*   adj   = (const int*)d_in[1];
    const float* W     = (const float*)d_in[2];
    const float* a     = (const float*)d_in[3];
    const float* gamma = (const float*)d_in[4];
    const float* beta  = (const float*)d_in[5];
    float* out = (float*)d_out;

    pack_adj_kernel<<<2048, 256>>>(adj);

    size_t gshmem = GSM * sizeof(float);
    cudaFuncSetAttribute(gemm_h_mma, cudaFuncAttributeMaxDynamicSharedMemorySize,
                         (int)gshmem);
    gemm_h_mma<<<dim3(64, 2), 256, gshmem>>>(x, W);

    prep_kernel<<<512, 256>>>(a);

    cudaFuncSetAttribute(attn_kernel, cudaFuncAttributeMaxDynamicSharedMemorySize,
                         SMEMB);
    attn_kernel<<<dim3(64, 4, 2), 256, SMEMB>>>();

    ln_kernel<<<512, 256>>>(gamma, beta, out);
}